// round 12
// baseline (speedup 1.0000x reference)
#include <cuda_runtime.h>
#include <mma.h>
#include <math.h>

using namespace nvcuda;

#define NB 4
#define NT1 16
#define NJ 17
#define NBT 64
#define NBJ 68
#define NROW 1088
#define NV 8000
#define NVPAD 8192
#define NE 256
#define NH 256
#define NENC 512
#define NS 5
#define EOSI 2

__device__ float d_eo[NBT * NENC];
__device__ float d_pb[2 * NH];
__device__ float d_wpT[NENC * 2 * NH];
__device__ float d_h0c0[NBT * 2 * NH];
__device__ float d_wih0T[512 * 1024];
__device__ float d_whh0T[256 * 1024];
__device__ float d_w1T[512 * 1024];
__device__ float d_fcT[256 * NV];
__device__ float d_xemb[NS * NBJ * NE];
__device__ float d_gx[384 * 1024];           // padded to 384 rows (6*64)
__device__ float d_gctx[NBT * 1024];
__device__ float d_h1[NROW * NH];
__device__ float d_c1[NROW * NH];
__device__ float d_h2[NROW * NH];
__device__ float d_c2[NROW * NH];
__device__ float d_g[NROW * 1024];
__device__ float d_logits[NROW * NVPAD];     // padded cols
__device__ float d_sel[NS * NROW];
__device__ float d_eosp[NS * NROW];

__device__ __forceinline__ float fast_tanh(float x)
{
    float y;
    asm("tanh.approx.f32 %0, %1;" : "=f"(y) : "f"(x));
    return y;
}
__device__ __forceinline__ float fast_sig(float x)
{
    return 0.5f * fast_tanh(0.5f * x) + 0.5f;
}

__global__ void k_transpose(const float* __restrict__ in, int N, int K,
                            float* __restrict__ out, int ldOut)
{
    __shared__ float t[32][33];
    int n0 = blockIdx.y * 32, k0 = blockIdx.x * 32;
    int tx = threadIdx.x, ty = threadIdx.y;
    #pragma unroll
    for (int i = 0; i < 32; i += 8) {
        int n = n0 + ty + i, k = k0 + tx;
        t[ty + i][tx] = (n < N && k < K) ? in[(size_t)n * K + k] : 0.f;
    }
    __syncthreads();
    #pragma unroll
    for (int i = 0; i < 32; i += 8) {
        int k = k0 + ty + i, n = n0 + tx;
        if (k < K && n < N) out[(size_t)k * ldOut + n] = t[tx][ty + i];
    }
}

__global__ void k_prep(const float* __restrict__ enc, const float* __restrict__ phb,
                       const float* __restrict__ pcb)
{
    int idx = blockIdx.x * 256 + threadIdx.x;
    int bt = idx >> 9, k = idx & 511;
    int b = bt >> 4, t1 = bt & 15;
    d_eo[idx] = enc[(t1 * NB + b) * NENC + k];
    if (idx < 512) d_pb[idx] = (idx < 256) ? phb[idx] : pcb[idx - 256];
}

__global__ void k_xemb(const int* __restrict__ prev, const float* __restrict__ embed,
                       const float* __restrict__ start_embed)
{
    int idx = blockIdx.x * 256 + threadIdx.x;
    int r = idx >> 8, n = idx & 255;
    int s = r / NBJ, bj = r % NBJ;
    int b = bj / NJ, j = bj % NJ;
    float v;
    if (s == 0) v = start_embed[n];
    else {
        int t = j + s - 1; if (t > 15) t = 15;
        v = embed[(size_t)prev[b * 16 + t] * NE + n];
    }
    d_xemb[idx] = v;
}

__global__ void k_init()
{
    int idx = blockIdx.x * 256 + threadIdx.x;
    int row = idx >> 8, n = idx & 255;
    int bt = row / NJ;
    d_h1[idx] = d_h0c0[bt * 512 + n];
    d_c1[idx] = d_h0c0[bt * 512 + 256 + n];
    d_h2[idx] = 0.f;
    d_c2[idx] = 0.f;
}

// fp32 fallback GEMM for the small one-time prep GEMMs (with bias).
__global__ __launch_bounds__(256) void k_gemm(
    const float* __restrict__ A, int lda,
    const float* __restrict__ A2, int lda2, int K1, int K,
    const float* __restrict__ WT, int ldw, int Nvalid,
    const float* __restrict__ bias,
    float* __restrict__ C, int ldc, int M)
{
    __shared__ float  As[16][68];
    __shared__ float4 Ws[16 * 64];
    int tid = threadIdx.x;
    int n0 = blockIdx.x * 256, r0 = blockIdx.y * 64;
    int tr = tid & 7, tc = tid >> 3;
    int rr = tid >> 2, kk = tid & 3;
    int gr = r0 + rr;
    float acc[8][8];
    #pragma unroll
    for (int i = 0; i < 8; i++)
        #pragma unroll
        for (int j = 0; j < 8; j++) acc[i][j] = 0.f;

    for (int kc = 0; kc < K; kc += 16) {
        int kg = kc + kk * 4;
        float4 av = make_float4(0.f, 0.f, 0.f, 0.f);
        if (gr < M) {
            const float* ap = (kg < K1) ? (A + (size_t)gr * lda + kg)
                                        : (A2 + (size_t)gr * lda2 + (kg - K1));
            av = *(const float4*)ap;
        }
        float4 wv[4];
        #pragma unroll
        for (int j = 0; j < 4; j++) {
            int pos = tid + j * 256;
            int k = pos >> 6, c4 = pos & 63;
            int n = n0 + c4 * 4;
            wv[j] = (n < Nvalid) ? *(const float4*)(WT + (size_t)(kc + k) * ldw + n)
                                 : make_float4(0.f, 0.f, 0.f, 0.f);
        }
        __syncthreads();
        As[kk * 4 + 0][rr] = av.x; As[kk * 4 + 1][rr] = av.y;
        As[kk * 4 + 2][rr] = av.z; As[kk * 4 + 3][rr] = av.w;
        #pragma unroll
        for (int j = 0; j < 4; j++) Ws[tid + j * 256] = wv[j];
        __syncthreads();
        #pragma unroll
        for (int k = 0; k < 16; k++) {
            float4 a0 = *(const float4*)&As[k][tr * 8];
            float4 a1 = *(const float4*)&As[k][tr * 8 + 4];
            float4 w0 = Ws[k * 64 + tc * 2];
            float4 w1 = Ws[k * 64 + tc * 2 + 1];
            float a[8] = {a0.x, a0.y, a0.z, a0.w, a1.x, a1.y, a1.z, a1.w};
            float w[8] = {w0.x, w0.y, w0.z, w0.w, w1.x, w1.y, w1.z, w1.w};
            #pragma unroll
            for (int i = 0; i < 8; i++)
                #pragma unroll
                for (int j = 0; j < 8; j++)
                    acc[i][j] += a[i] * w[j];
        }
        __syncthreads();
    }
    #pragma unroll
    for (int j = 0; j < 8; j++) {
        int n = n0 + tc * 8 + j;
        if (n >= Nvalid) continue;
        float bb = bias ? bias[n] : 0.f;
        #pragma unroll
        for (int i = 0; i < 8; i++) {
            int r = r0 + tr * 8 + i;
            if (r < M) C[(size_t)r * ldc + n] = acc[i][j] + bb;
        }
    }
}

// tf32 wmma GEMM: C[M x Nvalid(ceil)] = A_spliced[M x K] @ WT(k-major [K][ldw])
// Block tile 64x256, 8 warps (2x4), warp tile 32x64, k-chunk 32.
__global__ __launch_bounds__(256) void k_wgemm(
    const float* __restrict__ A, int lda,
    const float* __restrict__ A2, int lda2, int K1, int K,
    const float* __restrict__ WT, int ldw, int Nvalid,
    float* __restrict__ C, int ldc, int M)
{
    __shared__ float As[64 * 32];
    __shared__ float Ws[32 * 256];
    int tid = threadIdx.x;
    int wid = tid >> 5;
    int warp_m = wid & 1, warp_n = wid >> 1;
    int n0 = blockIdx.x * 256, r0 = blockIdx.y * 64;

    wmma::fragment<wmma::accumulator, 16, 16, 8, float> c_frag[2][4];
    #pragma unroll
    for (int i = 0; i < 2; i++)
        #pragma unroll
        for (int j = 0; j < 4; j++) wmma::fill_fragment(c_frag[i][j], 0.f);

    int arow = tid >> 2;              // 0..63
    int acol = (tid & 3) * 8;         // 0,8,16,24
    int gr = r0 + arow;
    int wrow = tid >> 3;              // 0..31
    int wcol = (tid & 7) * 32;        // 0..224

    for (int kc = 0; kc < K; kc += 32) {
        #pragma unroll
        for (int q = 0; q < 2; q++) {
            int kg = kc + acol + q * 4;
            float4 v = make_float4(0.f, 0.f, 0.f, 0.f);
            if (gr < M) {
                const float* ap = (kg < K1) ? (A + (size_t)gr * lda + kg)
                                            : (A2 + (size_t)gr * lda2 + (kg - K1));
                v = *(const float4*)ap;
            }
            *(float4*)&As[arow * 32 + acol + q * 4] = v;
        }
        #pragma unroll
        for (int q = 0; q < 8; q++) {
            int n = n0 + wcol + q * 4;
            float4 v = (n < Nvalid) ? *(const float4*)&WT[(size_t)(kc + wrow) * ldw + n]
                                    : make_float4(0.f, 0.f, 0.f, 0.f);
            *(float4*)&Ws[wrow * 256 + wcol + q * 4] = v;
        }
        __syncthreads();
        #pragma unroll
        for (int ks = 0; ks < 32; ks += 8) {
            wmma::fragment<wmma::matrix_a, 16, 16, 8, wmma::precision::tf32, wmma::row_major> a_frag[2];
            wmma::fragment<wmma::matrix_b, 16, 16, 8, wmma::precision::tf32, wmma::row_major> b_frag[4];
            #pragma unroll
            for (int i = 0; i < 2; i++) {
                wmma::load_matrix_sync(a_frag[i], &As[(warp_m * 32 + i * 16) * 32 + ks], 32);
                #pragma unroll
                for (int e = 0; e < a_frag[i].num_elements; e++)
                    a_frag[i].x[e] = wmma::__float_to_tf32(a_frag[i].x[e]);
            }
            #pragma unroll
            for (int j = 0; j < 4; j++) {
                wmma::load_matrix_sync(b_frag[j], &Ws[ks * 256 + warp_n * 64 + j * 16], 256);
                #pragma unroll
                for (int e = 0; e < b_frag[j].num_elements; e++)
                    b_frag[j].x[e] = wmma::__float_to_tf32(b_frag[j].x[e]);
            }
            #pragma unroll
            for (int i = 0; i < 2; i++)
                #pragma unroll
                for (int j = 0; j < 4; j++)
                    wmma::mma_sync(c_frag[i][j], a_frag[i], b_frag[j], c_frag[i][j]);
        }
        __syncthreads();
    }
    #pragma unroll
    for (int i = 0; i < 2; i++)
        #pragma unroll
        for (int j = 0; j < 4; j++) {
            int r = r0 + warp_m * 32 + i * 16;
            int n = n0 + warp_n * 64 + j * 16;
            wmma::store_matrix_sync(&C[(size_t)r * ldc + n], c_frag[i][j], ldc, wmma::mem_row_major);
        }
}

// Row LSE over logits (+bias) with target/EOS gather -> sel/eosp
__global__ __launch_bounds__(256) void k_lse(const float* __restrict__ fcb,
                                             const int* __restrict__ prev, int s)
{
    __shared__ float red[256];
    __shared__ float s_lt, s_le;
    int r = blockIdx.x, tid = threadIdx.x;
    const float* row = d_logits + (size_t)r * NVPAD;
    int b = r / 272, jj = (r % 272) % NJ;
    int t = jj + s; if (t > 15) t = 15;
    int tgtv = (s < 4) ? prev[b * 16 + t] : 0;

    float m = -INFINITY;
    for (int c = tid; c < NV; c += 256) {
        float v = row[c] + fcb[c];
        if (c == tgtv) s_lt = v;
        if (c == EOSI) s_le = v;
        m = fmaxf(m, v);
    }
    red[tid] = m; __syncthreads();
    #pragma unroll
    for (int o = 128; o > 0; o >>= 1) {
        if (tid < o) red[tid] = fmaxf(red[tid], red[tid + o]);
        __syncthreads();
    }
    float mx = red[0];
    __syncthreads();
    float ss = 0.f;
    for (int c = tid; c < NV; c += 256) ss += __expf(row[c] + fcb[c] - mx);
    red[tid] = ss; __syncthreads();
    #pragma unroll
    for (int o = 128; o > 0; o >>= 1) {
        if (tid < o) red[tid] += red[tid + o];
        __syncthreads();
    }
    if (tid == 0) {
        float lse = mx + __logf(red[0]);
        d_sel[s * NROW + r]  = s_lt - lse;
        d_eosp[s * NROW + r] = s_le - lse;
    }
}

__global__ void k_cell0(int s)
{
    int idx = blockIdx.x * 256 + threadIdx.x;
    int row = idx >> 8, n = idx & 255;
    int bt = row / NJ, j = row % NJ;
    int bj = (bt >> 4) * NJ + j;
    const float* gr  = d_g    + (size_t)row * 1024;
    const float* gc  = d_gctx + (size_t)bt * 1024;
    const float* gxr = d_gx   + (size_t)(s * NBJ + bj) * 1024;
    float gi = gr[n]       + gc[n]       + gxr[n];
    float gf = gr[n + 256] + gc[n + 256] + gxr[n + 256];
    float gg = gr[n + 512] + gc[n + 512] + gxr[n + 512];
    float go = gr[n + 768] + gc[n + 768] + gxr[n + 768];
    float c = fast_sig(gf) * d_c1[idx] + fast_sig(gi) * fast_tanh(gg);
    float h = fast_sig(go) * fast_tanh(c);
    d_c1[idx] = c; d_h1[idx] = h;
}

__global__ void k_cell1(const float* __restrict__ b1)
{
    int idx = blockIdx.x * 256 + threadIdx.x;
    int row = idx >> 8, n = idx & 255;
    const float* gr = d_g + (size_t)row * 1024;
    float gi = gr[n]       + b1[n];
    float gf = gr[n + 256] + b1[n + 256];
    float gg = gr[n + 512] + b1[n + 512];
    float go = gr[n + 768] + b1[n + 768];
    float c = fast_sig(gf) * d_c2[idx] + fast_sig(gi) * fast_tanh(gg);
    float h = fast_sig(go) * fast_tanh(c);
    d_c2[idx] = c; d_h2[idx] = h;
}

__global__ void k_dp(float* __restrict__ out)
{
    __shared__ float alpha[NB][NJ];
    __shared__ float alphan[NB][NJ];
    int tid = threadIdx.x;
    int b = tid >> 5, t = tid & 31;
    bool act = (b < NB && t < NJ);
    if (act) alpha[b][t] = (t == 0) ? 0.f : -1e30f;
    __syncthreads();
    for (int t1 = 0; t1 < NT1; t1++) {
        if (act) {
            float v[5], m = -INFINITY;
            #pragma unroll
            for (int k = 0; k < 5; k++) {
                if (k <= t) {
                    int j = t - k;
                    int row = (b * NT1 + t1) * NJ + j;
                    float cum = 0.f;
                    for (int ss = 0; ss < k; ss++) cum += d_sel[ss * NROW + row];
                    v[k] = alpha[b][j] + cum + d_eosp[k * NROW + row];
                } else v[k] = -INFINITY;
                m = fmaxf(m, v[k]);
            }
            float ssum = 0.f;
            #pragma unroll
            for (int k = 0; k < 5; k++) ssum += expf(v[k] - m);
            alphan[b][t] = m + logf(ssum);
        }
        __syncthreads();
        if (act) alpha[b][t] = alphan[b][t];
        __syncthreads();
    }
    if (act && t == NT1) out[b] = alpha[b][NT1];
}

extern "C" void kernel_launch(void* const* d_in, const int* in_sizes, int n_in,
                              void* d_out, int out_size)
{
    const int*   prev   = (const int*)  d_in[0];
    const float* enc    = (const float*)d_in[1];
    const float* embed  = (const float*)d_in[2];
    const float* stemb  = (const float*)d_in[3];
    const float* phw    = (const float*)d_in[4];
    const float* phb    = (const float*)d_in[5];
    const float* pcw    = (const float*)d_in[6];
    const float* pcb    = (const float*)d_in[7];
    const float* wih0   = (const float*)d_in[8];
    const float* whh0   = (const float*)d_in[9];
    const float* b0     = (const float*)d_in[10];
    const float* wih1   = (const float*)d_in[11];
    const float* whh1   = (const float*)d_in[12];
    const float* b1     = (const float*)d_in[13];
    const float* fcw    = (const float*)d_in[14];
    const float* fcb    = (const float*)d_in[15];
    float* out = (float*)d_out;

    float *p_eo, *p_pb, *p_wpT, *p_h0c0, *p_wih0T, *p_whh0T, *p_w1T, *p_fcT;
    float *p_xemb, *p_gx, *p_gctx, *p_h1, *p_h2, *p_g, *p_logits;
    cudaGetSymbolAddress((void**)&p_eo, d_eo);
    cudaGetSymbolAddress((void**)&p_pb, d_pb);
    cudaGetSymbolAddress((void**)&p_wpT, d_wpT);
    cudaGetSymbolAddress((void**)&p_h0c0, d_h0c0);
    cudaGetSymbolAddress((void**)&p_wih0T, d_wih0T);
    cudaGetSymbolAddress((void**)&p_whh0T, d_whh0T);
    cudaGetSymbolAddress((void**)&p_w1T, d_w1T);
    cudaGetSymbolAddress((void**)&p_fcT, d_fcT);
    cudaGetSymbolAddress((void**)&p_xemb, d_xemb);
    cudaGetSymbolAddress((void**)&p_gx, d_gx);
    cudaGetSymbolAddress((void**)&p_gctx, d_gctx);
    cudaGetSymbolAddress((void**)&p_h1, d_h1);
    cudaGetSymbolAddress((void**)&p_h2, d_h2);
    cudaGetSymbolAddress((void**)&p_g, d_g);
    cudaGetSymbolAddress((void**)&p_logits, d_logits);

    dim3 tb(32, 8);
    k_prep<<<128, 256>>>(enc, phb, pcb);
    k_transpose<<<dim3(16, 8),  tb>>>(phw,  256, 512, p_wpT, 512);
    k_transpose<<<dim3(16, 8),  tb>>>(pcw,  256, 512, p_wpT + 256, 512);
    k_transpose<<<dim3(16, 32), tb>>>(wih0, 1024, 512, p_wih0T, 1024);
    k_transpose<<<dim3(8, 32),  tb>>>(whh0, 1024, 256, p_whh0T, 1024);
    k_transpose<<<dim3(8, 32),  tb>>>(wih1, 1024, 256, p_w1T, 1024);
    k_transpose<<<dim3(8, 32),  tb>>>(whh1, 1024, 256, p_w1T + 256 * 1024, 1024);
    k_transpose<<<dim3(8, 250), tb>>>(fcw,  NV, 256, p_fcT, NV);
    k_gemm<<<dim3(2, 1), 256>>>(p_eo, 512, p_eo, 512, 512, 512,
                                p_wpT, 512, 512, p_pb, p_h0c0, 512, NBT);
    k_gemm<<<dim3(4, 1), 256>>>(p_h0c0, 512, p_h0c0, 512, 256, 256,
                                p_wih0T, 1024, 1024, b0, p_gctx, 1024, NBT);
    k_xemb<<<340, 256>>>(prev, embed, stemb);
    k_gemm<<<dim3(4, 6), 256>>>(p_xemb, 256, p_xemb, 256, 256, 256,
                                p_wih0T + 256 * 1024, 1024, 1024, (const float*)0,
                                p_gx, 1024, NS * NBJ);
    k_init<<<1088, 256>>>();

    for (int s = 0; s < NS; s++) {
        k_wgemm<<<dim3(4, 17), 256>>>(p_h1, 256, p_h1, 256, 256, 256,
                                      p_whh0T, 1024, 1024, p_g, 1024, NROW);
        k_cell0<<<1088, 256>>>(s);
        k_wgemm<<<dim3(4, 17), 256>>>(p_h1, 256, p_h2, 256, 256, 512,
                                      p_w1T, 1024, 1024, p_g, 1024, NROW);
        k_cell1<<<1088, 256>>>(b1);
        k_wgemm<<<dim3(32, 17), 256>>>(p_h2, 256, p_h2, 256, 256, 256,
                                       p_fcT, NV, NV, p_logits, NVPAD, NROW);
        k_lse<<<1088, 256>>>(fcb, prev, s);
    }
    k_dp<<<1, 128>>>(out);
}

// round 13
// speedup vs baseline: 1.5069x; 1.5069x over previous
#include <cuda_runtime.h>
#include <math.h>

#define NB 4
#define NT1 16
#define NJ 17
#define NBT 64
#define NBJ 68
#define NROW 1088
#define NV 8000
#define NE 256
#define NH 256
#define NENC 512
#define NS 5
#define EOSI 2

__device__ float d_eo[NBT * NENC];
__device__ float d_pb[2 * NH];
__device__ float d_wpT[NENC * 2 * NH];
__device__ float d_h0c0[NBT * 2 * NH];
__device__ float d_wih0Tg[512 * 1024];   // gate-permuted cols: 4*unit+gate
__device__ float d_whh0Tg[256 * 1024];
__device__ float d_w1Tg[512 * 1024];
__device__ float d_fcT[256 * NV];
__device__ float d_pb0[1024];
__device__ float d_pb1[1024];
__device__ float d_xemb[NS * NBJ * NE];
__device__ float d_gx[NS * NBJ * 1024];
__device__ float d_gctx[NBT * 1024];
__device__ float d_h1[2 * NROW * NH];    // ping-pong
__device__ float d_c1[NROW * NH];
__device__ float d_h2[2 * NROW * NH];
__device__ float d_c2[NROW * NH];
__device__ float d_pm[32 * NROW];
__device__ float d_ps[32 * NROW];
__device__ float d_lt[NROW];
__device__ float d_le[NROW];
__device__ float d_sel[NS * NROW];
__device__ float d_eosp[NS * NROW];

__device__ __forceinline__ float esig(float x)
{
    return __fdividef(1.f, 1.f + __expf(-x));
}
__device__ __forceinline__ float etanh(float x)
{
    return 2.f * __fdividef(1.f, 1.f + __expf(-2.f * x)) - 1.f;
}

__global__ void k_transpose(const float* __restrict__ in, int N, int K,
                            float* __restrict__ out, int ldOut)
{
    __shared__ float t[32][33];
    int n0 = blockIdx.y * 32, k0 = blockIdx.x * 32;
    int tx = threadIdx.x, ty = threadIdx.y;
    #pragma unroll
    for (int i = 0; i < 32; i += 8) {
        int n = n0 + ty + i, k = k0 + tx;
        t[ty + i][tx] = (n < N && k < K) ? in[(size_t)n * K + k] : 0.f;
    }
    __syncthreads();
    #pragma unroll
    for (int i = 0; i < 32; i += 8) {
        int k = k0 + ty + i, n = n0 + tx;
        if (k < K && n < N) out[(size_t)k * ldOut + n] = t[tx][ty + i];
    }
}

// Transpose with gate permutation on the 1024-wide output dim: col -> 4*(col&255)+(col>>8)
__global__ void k_transpose_g(const float* __restrict__ in, int N, int K,
                              float* __restrict__ out)
{
    __shared__ float t[32][33];
    int n0 = blockIdx.y * 32, k0 = blockIdx.x * 32;
    int tx = threadIdx.x, ty = threadIdx.y;
    #pragma unroll
    for (int i = 0; i < 32; i += 8) {
        int n = n0 + ty + i, k = k0 + tx;
        t[ty + i][tx] = (n < N && k < K) ? in[(size_t)n * K + k] : 0.f;
    }
    __syncthreads();
    #pragma unroll
    for (int i = 0; i < 32; i += 8) {
        int k = k0 + ty + i, n = n0 + tx;
        if (k < K && n < N)
            out[(size_t)k * 1024 + 4 * (n & 255) + (n >> 8)] = t[tx][ty + i];
    }
}

__global__ void k_permb(const float* __restrict__ b0, const float* __restrict__ b1)
{
    int n = blockIdx.x * 256 + threadIdx.x;   // 0..2047
    if (n < 1024) d_pb0[4 * (n & 255) + (n >> 8)] = b0[n];
    else { int m = n - 1024; d_pb1[4 * (m & 255) + (m >> 8)] = b1[m]; }
}

__global__ void k_prep(const float* __restrict__ enc, const float* __restrict__ phb,
                       const float* __restrict__ pcb)
{
    int idx = blockIdx.x * 256 + threadIdx.x;   // 64*512
    int bt = idx >> 9, k = idx & 511;
    int b = bt >> 4, t1 = bt & 15;
    d_eo[idx] = enc[(t1 * NB + b) * NENC + k];
    if (idx < 512) d_pb[idx] = (idx < 256) ? phb[idx] : pcb[idx - 256];
}

__global__ void k_xemb(const int* __restrict__ prev, const float* __restrict__ embed,
                       const float* __restrict__ start_embed)
{
    int idx = blockIdx.x * 256 + threadIdx.x;   // 340*256
    int r = idx >> 8, n = idx & 255;
    int s = r / NBJ, bj = r % NBJ;
    int b = bj / NJ, j = bj % NJ;
    float v;
    if (s == 0) v = start_embed[n];
    else {
        int t = j + s - 1; if (t > 15) t = 15;
        v = embed[(size_t)prev[b * 16 + t] * NE + n];
    }
    d_xemb[idx] = v;
}

__global__ void k_init()
{
    int idx = blockIdx.x * 256 + threadIdx.x;   // 1088*256
    int row = idx >> 8, n = idx & 255;
    int bt = row / NJ;
    d_h1[idx] = d_h0c0[bt * 512 + n];           // buffer 0
    d_c1[idx] = d_h0c0[bt * 512 + 256 + n];
    d_h2[idx] = 0.f;                            // buffer 0
    d_c2[idx] = 0.f;
}

// Generic fp32 GEMM for one-time prep (with bias + guards). 64x256 tile.
__global__ __launch_bounds__(256) void k_gemm(
    const float* __restrict__ A, int lda,
    const float* __restrict__ A2, int lda2, int K1, int K,
    const float* __restrict__ WT, int ldw, int Nvalid,
    const float* __restrict__ bias,
    float* __restrict__ C, int ldc, int M)
{
    __shared__ float  As[16][68];
    __shared__ float4 Ws[16 * 64];
    int tid = threadIdx.x;
    int n0 = blockIdx.x * 256, r0 = blockIdx.y * 64;
    int tr = tid & 7, tc = tid >> 3;
    int rr = tid >> 2, kk = tid & 3;
    int gr = r0 + rr;
    float acc[8][8];
    #pragma unroll
    for (int i = 0; i < 8; i++)
        #pragma unroll
        for (int j = 0; j < 8; j++) acc[i][j] = 0.f;

    float4 av = make_float4(0.f, 0.f, 0.f, 0.f);
    float4 wv[4];
    {
        int kg = kk * 4;
        if (gr < M) {
            const float* ap = (kg < K1) ? (A + (size_t)gr * lda + kg)
                                        : (A2 + (size_t)gr * lda2 + (kg - K1));
            av = *(const float4*)ap;
        }
        #pragma unroll
        for (int j = 0; j < 4; j++) {
            int pos = tid + j * 256;
            int k = pos >> 6, c4 = pos & 63;
            int n = n0 + c4 * 4;
            wv[j] = (n < Nvalid) ? *(const float4*)(WT + (size_t)k * ldw + n)
                                 : make_float4(0.f, 0.f, 0.f, 0.f);
        }
    }
    for (int kc = 0; kc < K; kc += 16) {
        __syncthreads();
        As[kk * 4 + 0][rr] = av.x; As[kk * 4 + 1][rr] = av.y;
        As[kk * 4 + 2][rr] = av.z; As[kk * 4 + 3][rr] = av.w;
        #pragma unroll
        for (int j = 0; j < 4; j++) Ws[tid + j * 256] = wv[j];
        __syncthreads();
        if (kc + 16 < K) {
            int kg = kc + 16 + kk * 4;
            if (gr < M) {
                const float* ap = (kg < K1) ? (A + (size_t)gr * lda + kg)
                                            : (A2 + (size_t)gr * lda2 + (kg - K1));
                av = *(const float4*)ap;
            }
            #pragma unroll
            for (int j = 0; j < 4; j++) {
                int pos = tid + j * 256;
                int k = kc + 16 + (pos >> 6);
                int n = n0 + (pos & 63) * 4;
                wv[j] = (n < Nvalid) ? *(const float4*)(WT + (size_t)k * ldw + n)
                                     : make_float4(0.f, 0.f, 0.f, 0.f);
            }
        }
        #pragma unroll
        for (int k = 0; k < 16; k++) {
            float4 a0 = *(const float4*)&As[k][tr * 8];
            float4 a1 = *(const float4*)&As[k][tr * 8 + 4];
            float4 w0 = Ws[k * 64 + tc * 2];
            float4 w1 = Ws[k * 64 + tc * 2 + 1];
            float a[8] = {a0.x, a0.y, a0.z, a0.w, a1.x, a1.y, a1.z, a1.w};
            float w[8] = {w0.x, w0.y, w0.z, w0.w, w1.x, w1.y, w1.z, w1.w};
            #pragma unroll
            for (int i = 0; i < 8; i++)
                #pragma unroll
                for (int j = 0; j < 8; j++)
                    acc[i][j] += a[i] * w[j];
        }
    }
    #pragma unroll
    for (int j = 0; j < 8; j++) {
        int n = n0 + tc * 8 + j;
        if (n >= Nvalid) continue;
        float bb = bias ? bias[n] : 0.f;
        #pragma unroll
        for (int i = 0; i < 8; i++) {
            int r = r0 + tr * 8 + i;
            if (r < M) C[(size_t)r * ldc + n] = acc[i][j] + bb;
        }
    }
}

// Fused LSTM GEMM: gates = A_spliced[1088 x K] @ WTg (gate-permuted) + extras,
// then cell update in epilogue. M=1088 exact, N=1024 exact.
// layer0: gx != null -> extra = gctx (per bt), gx (per s,bj). layer1: extra = permuted b1.
__global__ __launch_bounds__(256) void k_lstm(
    const float* __restrict__ A, const float* __restrict__ A2, int K,
    const float* __restrict__ WT,
    const float* __restrict__ extra, const float* __restrict__ gx,
    float* __restrict__ cSt, float* __restrict__ hOut)
{
    __shared__ float  As[16][68];
    __shared__ float4 Ws[16 * 64];
    int tid = threadIdx.x;
    int n0 = blockIdx.x * 256, r0 = blockIdx.y * 64;
    int tr = tid & 7, tc = tid >> 3;
    int rr = tid >> 2, kk = tid & 3;
    int gr = r0 + rr;
    float acc[8][8];
    #pragma unroll
    for (int i = 0; i < 8; i++)
        #pragma unroll
        for (int j = 0; j < 8; j++) acc[i][j] = 0.f;

    float4 av; float4 wv[4];
    {
        int kg = kk * 4;
        const float* ap = (kg < 256) ? (A + (size_t)gr * 256 + kg)
                                     : (A2 + (size_t)gr * 256 + kg - 256);
        av = *(const float4*)ap;
        #pragma unroll
        for (int j = 0; j < 4; j++) {
            int pos = tid + j * 256;
            wv[j] = *(const float4*)(WT + (size_t)(pos >> 6) * 1024 + n0 + (pos & 63) * 4);
        }
    }
    for (int kc = 0; kc < K; kc += 16) {
        __syncthreads();
        As[kk * 4 + 0][rr] = av.x; As[kk * 4 + 1][rr] = av.y;
        As[kk * 4 + 2][rr] = av.z; As[kk * 4 + 3][rr] = av.w;
        #pragma unroll
        for (int j = 0; j < 4; j++) Ws[tid + j * 256] = wv[j];
        __syncthreads();
        if (kc + 16 < K) {
            int kg = kc + 16 + kk * 4;
            const float* ap = (kg < 256) ? (A + (size_t)gr * 256 + kg)
                                         : (A2 + (size_t)gr * 256 + kg - 256);
            av = *(const float4*)ap;
            #pragma unroll
            for (int j = 0; j < 4; j++) {
                int pos = tid + j * 256;
                wv[j] = *(const float4*)(WT + (size_t)(kc + 16 + (pos >> 6)) * 1024 + n0 + (pos & 63) * 4);
            }
        }
        #pragma unroll
        for (int k = 0; k < 16; k++) {
            float4 a0 = *(const float4*)&As[k][tr * 8];
            float4 a1 = *(const float4*)&As[k][tr * 8 + 4];
            float4 w0 = Ws[k * 64 + tc * 2];
            float4 w1 = Ws[k * 64 + tc * 2 + 1];
            float a[8] = {a0.x, a0.y, a0.z, a0.w, a1.x, a1.y, a1.z, a1.w};
            float w[8] = {w0.x, w0.y, w0.z, w0.w, w1.x, w1.y, w1.z, w1.w};
            #pragma unroll
            for (int i = 0; i < 8; i++)
                #pragma unroll
                for (int j = 0; j < 8; j++)
                    acc[i][j] += a[i] * w[j];
        }
    }
    // epilogue: cell update. cols tc*8+uu*4+g = gates g of unit uBase+uu
    int uBase = (n0 >> 2) + tc * 2;
    #pragma unroll
    for (int i = 0; i < 8; i++) {
        int row = r0 + tr * 8 + i;
        int bt = row / 17;
        int jj = row - bt * 17;
        int b  = bt >> 4;
        #pragma unroll
        for (int uu = 0; uu < 2; uu++) {
            int u  = uBase + uu;
            int nb = n0 + tc * 8 + uu * 4;
            float gi = acc[i][uu * 4 + 0];
            float gf = acc[i][uu * 4 + 1];
            float gg = acc[i][uu * 4 + 2];
            float go = acc[i][uu * 4 + 3];
            if (gx) {
                const float* gc = extra + (size_t)bt * 1024 + nb;
                const float* gz = gx + (size_t)(b * 17 + jj) * 1024 + nb;
                gi += gc[0] + gz[0]; gf += gc[1] + gz[1];
                gg += gc[2] + gz[2]; go += gc[3] + gz[3];
            } else {
                gi += extra[nb]; gf += extra[nb + 1];
                gg += extra[nb + 2]; go += extra[nb + 3];
            }
            size_t off = (size_t)row * 256 + u;
            float c = esig(gf) * cSt[off] + esig(gi) * etanh(gg);
            cSt[off] = c;
            hOut[off] = esig(go) * etanh(c);
        }
    }
}

// FC GEMM fused with partial LSE + target/EOS logit gather (prefetched mainloop).
__global__ __launch_bounds__(256) void k_fc(
    const float* __restrict__ Ah2, const float* __restrict__ WT,
    const float* __restrict__ fcb, const int* __restrict__ prev, int s)
{
    __shared__ float  As[16][68];
    __shared__ float4 Ws[16 * 64];
    __shared__ float  red[64][33];
    __shared__ float  rowm[64];
    int tid = threadIdx.x;
    int n0 = blockIdx.x * 256, r0 = blockIdx.y * 64;
    int tr = tid & 7, tc = tid >> 3;
    int rr = tid >> 2, kk = tid & 3;
    float acc[8][8];
    #pragma unroll
    for (int i = 0; i < 8; i++)
        #pragma unroll
        for (int j = 0; j < 8; j++) acc[i][j] = 0.f;

    float4 av; float4 wv[4];
    av = *(const float4*)(Ah2 + (size_t)(r0 + rr) * 256 + kk * 4);
    #pragma unroll
    for (int j = 0; j < 4; j++) {
        int pos = tid + j * 256;
        int n = n0 + (pos & 63) * 4;
        wv[j] = (n < NV) ? *(const float4*)(WT + (size_t)(pos >> 6) * NV + n)
                         : make_float4(0.f, 0.f, 0.f, 0.f);
    }
    for (int kc = 0; kc < 256; kc += 16) {
        __syncthreads();
        As[kk * 4 + 0][rr] = av.x; As[kk * 4 + 1][rr] = av.y;
        As[kk * 4 + 2][rr] = av.z; As[kk * 4 + 3][rr] = av.w;
        #pragma unroll
        for (int j = 0; j < 4; j++) Ws[tid + j * 256] = wv[j];
        __syncthreads();
        if (kc + 16 < 256) {
            av = *(const float4*)(Ah2 + (size_t)(r0 + rr) * 256 + kc + 16 + kk * 4);
            #pragma unroll
            for (int j = 0; j < 4; j++) {
                int pos = tid + j * 256;
                int n = n0 + (pos & 63) * 4;
                wv[j] = (n < NV) ? *(const float4*)(WT + (size_t)(kc + 16 + (pos >> 6)) * NV + n)
                                 : make_float4(0.f, 0.f, 0.f, 0.f);
            }
        }
        #pragma unroll
        for (int k = 0; k < 16; k++) {
            float4 a0 = *(const float4*)&As[k][tr * 8];
            float4 a1 = *(const float4*)&As[k][tr * 8 + 4];
            float4 w0 = Ws[k * 64 + tc * 2];
            float4 w1 = Ws[k * 64 + tc * 2 + 1];
            float a[8] = {a0.x, a0.y, a0.z, a0.w, a1.x, a1.y, a1.z, a1.w};
            float w[8] = {w0.x, w0.y, w0.z, w0.w, w1.x, w1.y, w1.z, w1.w};
            #pragma unroll
            for (int i = 0; i < 8; i++)
                #pragma unroll
                for (int j = 0; j < 8; j++)
                    acc[i][j] += a[i] * w[j];
        }
    }
    bool cv[8];
    #pragma unroll
    for (int j = 0; j < 8; j++) {
        int n = n0 + tc * 8 + j;
        cv[j] = n < NV;
        float bb = cv[j] ? fcb[n] : 0.f;
        #pragma unroll
        for (int i = 0; i < 8; i++) acc[i][j] += bb;
    }
    #pragma unroll
    for (int i = 0; i < 8; i++) {
        int r = r0 + tr * 8 + i;
        int b = r / 272, jj = (r % 272) % NJ;
        int t = jj + s; if (t > 15) t = 15;
        int tgtv = (s < 4) ? prev[b * 16 + t] : 0;
        #pragma unroll
        for (int j = 0; j < 8; j++) {
            if (!cv[j]) continue;
            int n = n0 + tc * 8 + j;
            if (n == tgtv) d_lt[r] = acc[i][j];
            if (n == EOSI) d_le[r] = acc[i][j];
        }
    }
    #pragma unroll
    for (int i = 0; i < 8; i++) {
        float m = -INFINITY;
        #pragma unroll
        for (int j = 0; j < 8; j++) if (cv[j]) m = fmaxf(m, acc[i][j]);
        red[tr * 8 + i][tc] = m;
    }
    __syncthreads();
    if (tid < 64) {
        float m = -INFINITY;
        #pragma unroll
        for (int c = 0; c < 32; c++) m = fmaxf(m, red[tid][c]);
        rowm[tid] = m;
    }
    __syncthreads();
    #pragma unroll
    for (int i = 0; i < 8; i++) {
        float m = rowm[tr * 8 + i], ss = 0.f;
        #pragma unroll
        for (int j = 0; j < 8; j++) if (cv[j]) ss += __expf(acc[i][j] - m);
        red[tr * 8 + i][tc] = ss;
    }
    __syncthreads();
    if (tid < 64) {
        float ss = 0.f;
        #pragma unroll
        for (int c = 0; c < 32; c++) ss += red[tid][c];
        d_pm[blockIdx.x * NROW + r0 + tid] = rowm[tid];
        d_ps[blockIdx.x * NROW + r0 + tid] = ss;
    }
}

__global__ void k_combine(int s)
{
    int r = blockIdx.x * 256 + threadIdx.x;
    if (r >= NROW) return;
    float m = -INFINITY;
    #pragma unroll
    for (int ct = 0; ct < 32; ct++) m = fmaxf(m, d_pm[ct * NROW + r]);
    float ss = 0.f;
    #pragma unroll
    for (int ct = 0; ct < 32; ct++) ss += d_ps[ct * NROW + r] * __expf(d_pm[ct * NROW + r] - m);
    float lse = m + __logf(ss);
    d_sel[s * NROW + r]  = d_lt[r] - lse;
    d_eosp[s * NROW + r] = d_le[r] - lse;
}

__global__ void k_dp(float* __restrict__ out)
{
    __shared__ float alpha[NB][NJ];
    __shared__ float alphan[NB][NJ];
    int tid = threadIdx.x;
    int b = tid >> 5, t = tid & 31;
    bool act = (b < NB && t < NJ);
    if (act) alpha[b][t] = (t == 0) ? 0.f : -1e30f;
    __syncthreads();
    for (int t1 = 0; t1 < NT1; t1++) {
        if (act) {
            float v[5], m = -INFINITY;
            #pragma unroll
            for (int k = 0; k < 5; k++) {
                if (k <= t) {
                    int j = t - k;
                    int row = (b * NT1 + t1) * NJ + j;
                    float cum = 0.f;
                    for (int ss = 0; ss < k; ss++) cum += d_sel[ss * NROW + row];
                    v[k] = alpha[b][j] + cum + d_eosp[k * NROW + row];
                } else v[k] = -INFINITY;
                m = fmaxf(m, v[k]);
            }
            float ssum = 0.f;
            #pragma unroll
            for (int k = 0; k < 5; k++) ssum += expf(v[k] - m);
            alphan[b][t] = m + logf(ssum);
        }
        __syncthreads();
        if (act) alpha[b][t] = alphan[b][t];
        __syncthreads();
    }
    if (act && t == NT1) out[b] = alpha[b][NT1];
}

extern "C" void kernel_launch(void* const* d_in, const int* in_sizes, int n_in,
                              void* d_out, int out_size)
{
    const int*   prev   = (const int*)  d_in[0];
    const float* enc    = (const float*)d_in[1];
    const float* embed  = (const float*)d_in[2];
    const float* stemb  = (const float*)d_in[3];
    const float* phw    = (const float*)d_in[4];
    const float* phb    = (const float*)d_in[5];
    const float* pcw    = (const float*)d_in[6];
    const float* pcb    = (const float*)d_in[7];
    const float* wih0   = (const float*)d_in[8];
    const float* whh0   = (const float*)d_in[9];
    const float* b0     = (const float*)d_in[10];
    const float* wih1   = (const float*)d_in[11];
    const float* whh1   = (const float*)d_in[12];
    const float* b1     = (const float*)d_in[13];
    const float* fcw    = (const float*)d_in[14];
    const float* fcb    = (const float*)d_in[15];
    float* out = (float*)d_out;

    float *p_eo, *p_pb, *p_wpT, *p_h0c0, *p_wih0Tg, *p_whh0Tg, *p_w1Tg, *p_fcT;
    float *p_xemb, *p_gx, *p_gctx, *p_h1, *p_c1, *p_h2, *p_c2, *p_pb0, *p_pb1;
    cudaGetSymbolAddress((void**)&p_eo, d_eo);
    cudaGetSymbolAddress((void**)&p_pb, d_pb);
    cudaGetSymbolAddress((void**)&p_wpT, d_wpT);
    cudaGetSymbolAddress((void**)&p_h0c0, d_h0c0);
    cudaGetSymbolAddress((void**)&p_wih0Tg, d_wih0Tg);
    cudaGetSymbolAddress((void**)&p_whh0Tg, d_whh0Tg);
    cudaGetSymbolAddress((void**)&p_w1Tg, d_w1Tg);
    cudaGetSymbolAddress((void**)&p_fcT, d_fcT);
    cudaGetSymbolAddress((void**)&p_xemb, d_xemb);
    cudaGetSymbolAddress((void**)&p_gx, d_gx);
    cudaGetSymbolAddress((void**)&p_gctx, d_gctx);
    cudaGetSymbolAddress((void**)&p_h1, d_h1);
    cudaGetSymbolAddress((void**)&p_c1, d_c1);
    cudaGetSymbolAddress((void**)&p_h2, d_h2);
    cudaGetSymbolAddress((void**)&p_c2, d_c2);
    cudaGetSymbolAddress((void**)&p_pb0, d_pb0);
    cudaGetSymbolAddress((void**)&p_pb1, d_pb1);

    dim3 tb(32, 8);
    k_prep<<<128, 256>>>(enc, phb, pcb);
    k_transpose<<<dim3(16, 8),  tb>>>(phw,  256, 512, p_wpT, 512);
    k_transpose<<<dim3(16, 8),  tb>>>(pcw,  256, 512, p_wpT + 256, 512);
    k_transpose_g<<<dim3(16, 32), tb>>>(wih0, 1024, 512, p_wih0Tg);
    k_transpose_g<<<dim3(8, 32),  tb>>>(whh0, 1024, 256, p_whh0Tg);
    k_transpose_g<<<dim3(8, 32),  tb>>>(wih1, 1024, 256, p_w1Tg);
    k_transpose_g<<<dim3(8, 32),  tb>>>(whh1, 1024, 256, p_w1Tg + 256 * 1024);
    k_transpose<<<dim3(8, 250), tb>>>(fcw,  NV, 256, p_fcT, NV);
    k_permb<<<8, 256>>>(b0, b1);
    // h0|c0 = eo @ [proj_h|proj_c]^T + bias
    k_gemm<<<dim3(2, 1), 256>>>(p_eo, 512, p_eo, 512, 512, 512,
                                p_wpT, 512, 512, p_pb, p_h0c0, 512, NBT);
    // ctx gate preacts (+ permuted b0), gate-permuted cols
    k_gemm<<<dim3(4, 1), 256>>>(p_h0c0, 512, p_h0c0, 512, 256, 256,
                                p_wih0Tg, 1024, 1024, p_pb0, p_gctx, 1024, NBT);
    k_xemb<<<340, 256>>>(prev, embed, stemb);
    // x gate preacts, all steps, gate-permuted cols
    k_gemm<<<dim3(4, 6), 256>>>(p_xemb, 256, p_xemb, 256, 256, 256,
                                p_wih0Tg + 256 * 1024, 1024, 1024, (const float*)0,
                                p_gx, 1024, NS * NBJ);
    k_init<<<1088, 256>>>();

    const int HB = NROW * NH;
    for (int s = 0; s < NS; s++) {
        float* h1r = p_h1 + (s & 1) * HB;
        float* h1w = p_h1 + ((s + 1) & 1) * HB;
        float* h2r = p_h2 + (s & 1) * HB;
        float* h2w = p_h2 + ((s + 1) & 1) * HB;
        // layer0: gates = h1 @ whh0^T (+gctx +gx), cell -> h1w, c1
        k_lstm<<<dim3(4, 17), 256>>>(h1r, h1r, 256, p_whh0Tg,
                                     p_gctx, p_gx + (size_t)s * NBJ * 1024,
                                     p_c1, h1w);
        // layer1: gates = [h1w|h2r] @ [wih1|whh1]^T (+b1), cell -> h2w, c2
        k_lstm<<<dim3(4, 17), 256>>>(h1w, h2r, 512, p_w1Tg,
                                     p_pb1, (const float*)0,
                                     p_c2, h2w);
        k_fc<<<dim3(32, 17), 256>>>(h2w, p_fcT, fcb, prev, s);
        k_combine<<<5, 256>>>(s);
    }
    k_dp<<<1, 128>>>(out);
}

// round 16
// speedup vs baseline: 1.8276x; 1.2128x over previous
#include <cuda_runtime.h>
#include <math.h>

#define NB 4
#define NT1 16
#define NJ 17
#define NBT 64
#define NBJ 68
#define NROW 1088
#define NV 8000
#define NE 256
#define NH 256
#define NENC 512
#define NS 5
#define EOSI 2

__device__ float d_eo[NBT * NENC];
__device__ float d_pb[2 * NH];
__device__ float d_wpT[NENC * 2 * NH];
__device__ float d_h0c0[NBT * 2 * NH];
__device__ float d_wih0Tg[512 * 1024];   // gate-permuted cols: 4*unit+gate
__device__ float d_whh0Tg[256 * 1024];
__device__ float d_w1Tg[512 * 1024];
__device__ float d_fcT[256 * NV];
__device__ float d_pb0[1024];
__device__ float d_pb1[1024];
__device__ float d_xemb[NS * NBJ * NE];
__device__ float d_gx[NS * NBJ * 1024];
__device__ float d_gctx[NBT * 1024];
__device__ float d_h1[2 * NROW * NH];    // ping-pong
__device__ float d_c1[NROW * NH];
__device__ float d_h2[2 * NROW * NH];
__device__ float d_c2[NROW * NH];
__device__ float d_pm[32 * NROW];
__device__ float d_ps[32 * NROW];
__device__ float d_lt[NROW];
__device__ float d_le[NROW];
__device__ float d_sel[NS * NROW];
__device__ float d_eosp[NS * NROW];

__device__ __forceinline__ float esig(float x)
{
    return __fdividef(1.f, 1.f + __expf(-x));
}
__device__ __forceinline__ float etanh(float x)
{
    return 2.f * __fdividef(1.f, 1.f + __expf(-2.f * x)) - 1.f;
}

__global__ void k_transpose(const float* __restrict__ in, int N, int K,
                            float* __restrict__ out, int ldOut)
{
    __shared__ float t[32][33];
    int n0 = blockIdx.y * 32, k0 = blockIdx.x * 32;
    int tx = threadIdx.x, ty = threadIdx.y;
    #pragma unroll
    for (int i = 0; i < 32; i += 8) {
        int n = n0 + ty + i, k = k0 + tx;
        t[ty + i][tx] = (n < N && k < K) ? in[(size_t)n * K + k] : 0.f;
    }
    __syncthreads();
    #pragma unroll
    for (int i = 0; i < 32; i += 8) {
        int k = k0 + ty + i, n = n0 + tx;
        if (k < K && n < N) out[(size_t)k * ldOut + n] = t[tx][ty + i];
    }
}

// Transpose with gate permutation on the 1024-wide output dim: col -> 4*(col&255)+(col>>8)
__global__ void k_transpose_g(const float* __restrict__ in, int N, int K,
                              float* __restrict__ out)
{
    __shared__ float t[32][33];
    int n0 = blockIdx.y * 32, k0 = blockIdx.x * 32;
    int tx = threadIdx.x, ty = threadIdx.y;
    #pragma unroll
    for (int i = 0; i < 32; i += 8) {
        int n = n0 + ty + i, k = k0 + tx;
        t[ty + i][tx] = (n < N && k < K) ? in[(size_t)n * K + k] : 0.f;
    }
    __syncthreads();
    #pragma unroll
    for (int i = 0; i < 32; i += 8) {
        int k = k0 + ty + i, n = n0 + tx;
        if (k < K && n < N)
            out[(size_t)k * 1024 + 4 * (n & 255) + (n >> 8)] = t[tx][ty + i];
    }
}

__global__ void k_permb(const float* __restrict__ b0, const float* __restrict__ b1)
{
    int n = blockIdx.x * 256 + threadIdx.x;   // 0..2047
    if (n < 1024) d_pb0[4 * (n & 255) + (n >> 8)] = b0[n];
    else { int m = n - 1024; d_pb1[4 * (m & 255) + (m >> 8)] = b1[m]; }
}

__global__ void k_prep(const float* __restrict__ enc, const float* __restrict__ phb,
                       const float* __restrict__ pcb)
{
    int idx = blockIdx.x * 256 + threadIdx.x;   // 64*512
    int bt = idx >> 9, k = idx & 511;
    int b = bt >> 4, t1 = bt & 15;
    d_eo[idx] = enc[(t1 * NB + b) * NENC + k];
    if (idx < 512) d_pb[idx] = (idx < 256) ? phb[idx] : pcb[idx - 256];
}

__global__ void k_xemb(const int* __restrict__ prev, const float* __restrict__ embed,
                       const float* __restrict__ start_embed)
{
    int idx = blockIdx.x * 256 + threadIdx.x;   // 340*256
    int r = idx >> 8, n = idx & 255;
    int s = r / NBJ, bj = r % NBJ;
    int b = bj / NJ, j = bj % NJ;
    float v;
    if (s == 0) v = start_embed[n];
    else {
        int t = j + s - 1; if (t > 15) t = 15;
        v = embed[(size_t)prev[b * 16 + t] * NE + n];
    }
    d_xemb[idx] = v;
}

__global__ void k_init()
{
    int idx = blockIdx.x * 256 + threadIdx.x;   // 1088*256
    int row = idx >> 8, n = idx & 255;
    int bt = row / NJ;
    d_h1[idx] = d_h0c0[bt * 512 + n];           // buffer 0
    d_c1[idx] = d_h0c0[bt * 512 + 256 + n];
    d_h2[idx] = 0.f;                            // buffer 0
    d_c2[idx] = 0.f;
}

// Generic fp32 GEMM for one-time prep (with bias + guards). 64x256 tile.
__global__ __launch_bounds__(256) void k_gemm(
    const float* __restrict__ A, int lda,
    const float* __restrict__ A2, int lda2, int K1, int K,
    const float* __restrict__ WT, int ldw, int Nvalid,
    const float* __restrict__ bias,
    float* __restrict__ C, int ldc, int M)
{
    __shared__ float  As[16][68];
    __shared__ float4 Ws[16 * 64];
    int tid = threadIdx.x;
    int n0 = blockIdx.x * 256, r0 = blockIdx.y * 64;
    int tr = tid & 7, tc = tid >> 3;
    int rr = tid >> 2, kk = tid & 3;
    int gr = r0 + rr;
    float acc[8][8];
    #pragma unroll
    for (int i = 0; i < 8; i++)
        #pragma unroll
        for (int j = 0; j < 8; j++) acc[i][j] = 0.f;

    float4 av = make_float4(0.f, 0.f, 0.f, 0.f);
    float4 wv[4];
    {
        int kg = kk * 4;
        if (gr < M) {
            const float* ap = (kg < K1) ? (A + (size_t)gr * lda + kg)
                                        : (A2 + (size_t)gr * lda2 + (kg - K1));
            av = *(const float4*)ap;
        }
        #pragma unroll
        for (int j = 0; j < 4; j++) {
            int pos = tid + j * 256;
            int k = pos >> 6, c4 = pos & 63;
            int n = n0 + c4 * 4;
            wv[j] = (n < Nvalid) ? *(const float4*)(WT + (size_t)k * ldw + n)
                                 : make_float4(0.f, 0.f, 0.f, 0.f);
        }
    }
    for (int kc = 0; kc < K; kc += 16) {
        __syncthreads();
        As[kk * 4 + 0][rr] = av.x; As[kk * 4 + 1][rr] = av.y;
        As[kk * 4 + 2][rr] = av.z; As[kk * 4 + 3][rr] = av.w;
        #pragma unroll
        for (int j = 0; j < 4; j++) Ws[tid + j * 256] = wv[j];
        __syncthreads();
        if (kc + 16 < K) {
            int kg = kc + 16 + kk * 4;
            if (gr < M) {
                const float* ap = (kg < K1) ? (A + (size_t)gr * lda + kg)
                                            : (A2 + (size_t)gr * lda2 + (kg - K1));
                av = *(const float4*)ap;
            }
            #pragma unroll
            for (int j = 0; j < 4; j++) {
                int pos = tid + j * 256;
                int k = kc + 16 + (pos >> 6);
                int n = n0 + (pos & 63) * 4;
                wv[j] = (n < Nvalid) ? *(const float4*)(WT + (size_t)k * ldw + n)
                                     : make_float4(0.f, 0.f, 0.f, 0.f);
            }
        }
        #pragma unroll
        for (int k = 0; k < 16; k++) {
            float4 a0 = *(const float4*)&As[k][tr * 8];
            float4 a1 = *(const float4*)&As[k][tr * 8 + 4];
            float4 w0 = Ws[k * 64 + tc * 2];
            float4 w1 = Ws[k * 64 + tc * 2 + 1];
            float a[8] = {a0.x, a0.y, a0.z, a0.w, a1.x, a1.y, a1.z, a1.w};
            float w[8] = {w0.x, w0.y, w0.z, w0.w, w1.x, w1.y, w1.z, w1.w};
            #pragma unroll
            for (int i = 0; i < 8; i++)
                #pragma unroll
                for (int j = 0; j < 8; j++)
                    acc[i][j] += a[i] * w[j];
        }
    }
    #pragma unroll
    for (int j = 0; j < 8; j++) {
        int n = n0 + tc * 8 + j;
        if (n >= Nvalid) continue;
        float bb = bias ? bias[n] : 0.f;
        #pragma unroll
        for (int i = 0; i < 8; i++) {
            int r = r0 + tr * 8 + i;
            if (r < M) C[(size_t)r * ldc + n] = acc[i][j] + bb;
        }
    }
}

// Fused LSTM GEMM, 32-row tiles for full-chip occupancy (grid 4 x 34 = 136 CTAs).
// gates = A_spliced[1088 x K] @ WTg (gate-permuted), cell update in epilogue.
__global__ __launch_bounds__(256) void k_lstm(
    const float* __restrict__ A, const float* __restrict__ A2, int K,
    const float* __restrict__ WT,
    const float* __restrict__ extra, const float* __restrict__ gx,
    float* __restrict__ cSt, float* __restrict__ hOut)
{
    __shared__ float  As[16][36];
    __shared__ float4 Ws[16 * 64];
    int tid = threadIdx.x;
    int n0 = blockIdx.x * 256, r0 = blockIdx.y * 32;
    int tr = tid & 7, tc = tid >> 3;       // tr: 8 row-groups of 4, tc: 32 col-groups of 8
    int rr = tid >> 2, kk = tid & 3;       // A-loader (tid<128): 32 rows x 4 float4
    bool ald = tid < 128;
    int gr = r0 + rr;
    float acc[4][8];
    #pragma unroll
    for (int i = 0; i < 4; i++)
        #pragma unroll
        for (int j = 0; j < 8; j++) acc[i][j] = 0.f;

    float4 av = make_float4(0.f, 0.f, 0.f, 0.f);
    float4 wv[4];
    {
        if (ald) {
            int kg = kk * 4;
            const float* ap = (kg < 256) ? (A + (size_t)gr * 256 + kg)
                                         : (A2 + (size_t)gr * 256 + kg - 256);
            av = *(const float4*)ap;
        }
        #pragma unroll
        for (int j = 0; j < 4; j++) {
            int pos = tid + j * 256;
            wv[j] = *(const float4*)(WT + (size_t)(pos >> 6) * 1024 + n0 + (pos & 63) * 4);
        }
    }
    for (int kc = 0; kc < K; kc += 16) {
        __syncthreads();
        if (ald) {
            As[kk * 4 + 0][rr] = av.x; As[kk * 4 + 1][rr] = av.y;
            As[kk * 4 + 2][rr] = av.z; As[kk * 4 + 3][rr] = av.w;
        }
        #pragma unroll
        for (int j = 0; j < 4; j++) Ws[tid + j * 256] = wv[j];
        __syncthreads();
        if (kc + 16 < K) {
            if (ald) {
                int kg = kc + 16 + kk * 4;
                const float* ap = (kg < 256) ? (A + (size_t)gr * 256 + kg)
                                             : (A2 + (size_t)gr * 256 + kg - 256);
                av = *(const float4*)ap;
            }
            #pragma unroll
            for (int j = 0; j < 4; j++) {
                int pos = tid + j * 256;
                wv[j] = *(const float4*)(WT + (size_t)(kc + 16 + (pos >> 6)) * 1024 + n0 + (pos & 63) * 4);
            }
        }
        #pragma unroll
        for (int k = 0; k < 16; k++) {
            float4 a0 = *(const float4*)&As[k][tr * 4];
            float4 w0 = Ws[k * 64 + tc * 2];
            float4 w1 = Ws[k * 64 + tc * 2 + 1];
            float a[4] = {a0.x, a0.y, a0.z, a0.w};
            float w[8] = {w0.x, w0.y, w0.z, w0.w, w1.x, w1.y, w1.z, w1.w};
            #pragma unroll
            for (int i = 0; i < 4; i++)
                #pragma unroll
                for (int j = 0; j < 8; j++)
                    acc[i][j] += a[i] * w[j];
        }
    }
    // epilogue: cell update. cols tc*8+uu*4+g = gates g of unit uBase+uu
    int uBase = (n0 >> 2) + tc * 2;
    #pragma unroll
    for (int i = 0; i < 4; i++) {
        int row = r0 + tr * 4 + i;
        int bt = row / 17;
        int jj = row - bt * 17;
        int b  = bt >> 4;
        #pragma unroll
        for (int uu = 0; uu < 2; uu++) {
            int u  = uBase + uu;
            int nb = n0 + tc * 8 + uu * 4;
            float gi = acc[i][uu * 4 + 0];
            float gf = acc[i][uu * 4 + 1];
            float gg = acc[i][uu * 4 + 2];
            float go = acc[i][uu * 4 + 3];
            if (gx) {
                const float* gc = extra + (size_t)bt * 1024 + nb;
                const float* gz = gx + (size_t)(b * 17 + jj) * 1024 + nb;
                gi += gc[0] + gz[0]; gf += gc[1] + gz[1];
                gg += gc[2] + gz[2]; go += gc[3] + gz[3];
            } else {
                gi += extra[nb]; gf += extra[nb + 1];
                gg += extra[nb + 2]; go += extra[nb + 3];
            }
            size_t off = (size_t)row * 256 + u;
            float c = esig(gf) * cSt[off] + esig(gi) * etanh(gg);
            cSt[off] = c;
            hOut[off] = esig(go) * etanh(c);
        }
    }
}

// FC GEMM fused with partial LSE + target/EOS logit gather (prefetched mainloop).
__global__ __launch_bounds__(256) void k_fc(
    const float* __restrict__ Ah2, const float* __restrict__ WT,
    const float* __restrict__ fcb, const int* __restrict__ prev, int s)
{
    __shared__ float  As[16][68];
    __shared__ float4 Ws[16 * 64];
    __shared__ float  red[64][33];
    __shared__ float  rowm[64];
    int tid = threadIdx.x;
    int n0 = blockIdx.x * 256, r0 = blockIdx.y * 64;
    int tr = tid & 7, tc = tid >> 3;
    int rr = tid >> 2, kk = tid & 3;
    float acc[8][8];
    #pragma unroll
    for (int i = 0; i < 8; i++)
        #pragma unroll
        for (int j = 0; j < 8; j++) acc[i][j] = 0.f;

    float4 av; float4 wv[4];
    av = *(const float4*)(Ah2 + (size_t)(r0 + rr) * 256 + kk * 4);
    #pragma unroll
    for (int j = 0; j < 4; j++) {
        int pos = tid + j * 256;
        int n = n0 + (pos & 63) * 4;
        wv[j] = (n < NV) ? *(const float4*)(WT + (size_t)(pos >> 6) * NV + n)
                         : make_float4(0.f, 0.f, 0.f, 0.f);
    }
    for (int kc = 0; kc < 256; kc += 16) {
        __syncthreads();
        As[kk * 4 + 0][rr] = av.x; As[kk * 4 + 1][rr] = av.y;
        As[kk * 4 + 2][rr] = av.z; As[kk * 4 + 3][rr] = av.w;
        #pragma unroll
        for (int j = 0; j < 4; j++) Ws[tid + j * 256] = wv[j];
        __syncthreads();
        if (kc + 16 < 256) {
            av = *(const float4*)(Ah2 + (size_t)(r0 + rr) * 256 + kc + 16 + kk * 4);
            #pragma unroll
            for (int j = 0; j < 4; j++) {
                int pos = tid + j * 256;
                int n = n0 + (pos & 63) * 4;
                wv[j] = (n < NV) ? *(const float4*)(WT + (size_t)(kc + 16 + (pos >> 6)) * NV + n)
                                 : make_float4(0.f, 0.f, 0.f, 0.f);
            }
        }
        #pragma unroll
        for (int k = 0; k < 16; k++) {
            float4 a0 = *(const float4*)&As[k][tr * 8];
            float4 a1 = *(const float4*)&As[k][tr * 8 + 4];
            float4 w0 = Ws[k * 64 + tc * 2];
            float4 w1 = Ws[k * 64 + tc * 2 + 1];
            float a[8] = {a0.x, a0.y, a0.z, a0.w, a1.x, a1.y, a1.z, a1.w};
            float w[8] = {w0.x, w0.y, w0.z, w0.w, w1.x, w1.y, w1.z, w1.w};
            #pragma unroll
            for (int i = 0; i < 8; i++)
                #pragma unroll
                for (int j = 0; j < 8; j++)
                    acc[i][j] += a[i] * w[j];
        }
    }
    bool cv[8];
    #pragma unroll
    for (int j = 0; j < 8; j++) {
        int n = n0 + tc * 8 + j;
        cv[j] = n < NV;
        float bb = cv[j] ? fcb[n] : 0.f;
        #pragma unroll
        for (int i = 0; i < 8; i++) acc[i][j] += bb;
    }
    #pragma unroll
    for (int i = 0; i < 8; i++) {
        int r = r0 + tr * 8 + i;
        int b = r / 272, jj = (r % 272) % NJ;
        int t = jj + s; if (t > 15) t = 15;
        int tgtv = (s < 4) ? prev[b * 16 + t] : 0;
        #pragma unroll
        for (int j = 0; j < 8; j++) {
            if (!cv[j]) continue;
            int n = n0 + tc * 8 + j;
            if (n == tgtv) d_lt[r] = acc[i][j];
            if (n == EOSI) d_le[r] = acc[i][j];
        }
    }
    #pragma unroll
    for (int i = 0; i < 8; i++) {
        float m = -INFINITY;
        #pragma unroll
        for (int j = 0; j < 8; j++) if (cv[j]) m = fmaxf(m, acc[i][j]);
        red[tr * 8 + i][tc] = m;
    }
    __syncthreads();
    if (tid < 64) {
        float m = -INFINITY;
        #pragma unroll
        for (int c = 0; c < 32; c++) m = fmaxf(m, red[tid][c]);
        rowm[tid] = m;
    }
    __syncthreads();
    #pragma unroll
    for (int i = 0; i < 8; i++) {
        float m = rowm[tr * 8 + i], ss = 0.f;
        #pragma unroll
        for (int j = 0; j < 8; j++) if (cv[j]) ss += __expf(acc[i][j] - m);
        red[tr * 8 + i][tc] = ss;
    }
    __syncthreads();
    if (tid < 64) {
        float ss = 0.f;
        #pragma unroll
        for (int c = 0; c < 32; c++) ss += red[tid][c];
        d_pm[blockIdx.x * NROW + r0 + tid] = rowm[tid];
        d_ps[blockIdx.x * NROW + r0 + tid] = ss;
    }
}

__global__ void k_combine(int s)
{
    int r = blockIdx.x * 256 + threadIdx.x;
    if (r >= NROW) return;
    float m = -INFINITY;
    #pragma unroll
    for (int ct = 0; ct < 32; ct++) m = fmaxf(m, d_pm[ct * NROW + r]);
    float ss = 0.f;
    #pragma unroll
    for (int ct = 0; ct < 32; ct++) ss += d_ps[ct * NROW + r] * __expf(d_pm[ct * NROW + r] - m);
    float lse = m + __logf(ss);
    d_sel[s * NROW + r]  = d_lt[r] - lse;
    d_eosp[s * NROW + r] = d_le[r] - lse;
}

__global__ void k_dp(float* __restrict__ out)
{
    __shared__ float alpha[NB][NJ];
    __shared__ float alphan[NB][NJ];
    int tid = threadIdx.x;
    int b = tid >> 5, t = tid & 31;
    bool act = (b < NB && t < NJ);
    if (act) alpha[b][t] = (t == 0) ? 0.f : -1e30f;
    __syncthreads();
    for (int t1 = 0; t1 < NT1; t1++) {
        if (act) {
            float v[5], m = -INFINITY;
            #pragma unroll
            for (int k = 0; k < 5; k++) {
                if (k <= t) {
                    int j = t - k;
                    int row = (b * NT1 + t1) * NJ + j;
                    float cum = 0.f;
                    for (int ss = 0; ss < k; ss++) cum += d_sel[ss * NROW + row];
                    v[k] = alpha[b][j] + cum + d_eosp[k * NROW + row];
                } else v[k] = -INFINITY;
                m = fmaxf(m, v[k]);
            }
            float ssum = 0.f;
            #pragma unroll
            for (int k = 0; k < 5; k++) ssum += expf(v[k] - m);
            alphan[b][t] = m + logf(ssum);
        }
        __syncthreads();
        if (act) alpha[b][t] = alphan[b][t];
        __syncthreads();
    }
    if (act && t == NT1) out[b] = alpha[b][NT1];
}

extern "C" void kernel_launch(void* const* d_in, const int* in_sizes, int n_in,
                              void* d_out, int out_size)
{
    const int*   prev   = (const int*)  d_in[0];
    const float* enc    = (const float*)d_in[1];
    const float* embed  = (const float*)d_in[2];
    const float* stemb  = (const float*)d_in[3];
    const float* phw    = (const float*)d_in[4];
    const float* phb    = (const float*)d_in[5];
    const float* pcw    = (const float*)d_in[6];
    const float* pcb    = (const float*)d_in[7];
    const float* wih0   = (const float*)d_in[8];
    const float* whh0   = (const float*)d_in[9];
    const float* b0     = (const float*)d_in[10];
    const float* wih1   = (const float*)d_in[11];
    const float* whh1   = (const float*)d_in[12];
    const float* b1     = (const float*)d_in[13];
    const float* fcw    = (const float*)d_in[14];
    const float* fcb    = (const float*)d_in[15];
    float* out = (float*)d_out;

    float *p_eo, *p_pb, *p_wpT, *p_h0c0, *p_wih0Tg, *p_whh0Tg, *p_w1Tg, *p_fcT;
    float *p_xemb, *p_gx, *p_gctx, *p_h1, *p_c1, *p_h2, *p_c2, *p_pb0, *p_pb1;
    cudaGetSymbolAddress((void**)&p_eo, d_eo);
    cudaGetSymbolAddress((void**)&p_pb, d_pb);
    cudaGetSymbolAddress((void**)&p_wpT, d_wpT);
    cudaGetSymbolAddress((void**)&p_h0c0, d_h0c0);
    cudaGetSymbolAddress((void**)&p_wih0Tg, d_wih0Tg);
    cudaGetSymbolAddress((void**)&p_whh0Tg, d_whh0Tg);
    cudaGetSymbolAddress((void**)&p_w1Tg, d_w1Tg);
    cudaGetSymbolAddress((void**)&p_fcT, d_fcT);
    cudaGetSymbolAddress((void**)&p_xemb, d_xemb);
    cudaGetSymbolAddress((void**)&p_gx, d_gx);
    cudaGetSymbolAddress((void**)&p_gctx, d_gctx);
    cudaGetSymbolAddress((void**)&p_h1, d_h1);
    cudaGetSymbolAddress((void**)&p_c1, d_c1);
    cudaGetSymbolAddress((void**)&p_h2, d_h2);
    cudaGetSymbolAddress((void**)&p_c2, d_c2);
    cudaGetSymbolAddress((void**)&p_pb0, d_pb0);
    cudaGetSymbolAddress((void**)&p_pb1, d_pb1);

    dim3 tb(32, 8);
    k_prep<<<128, 256>>>(enc, phb, pcb);
    k_transpose<<<dim3(16, 8),  tb>>>(phw,  256, 512, p_wpT, 512);
    k_transpose<<<dim3(16, 8),  tb>>>(pcw,  256, 512, p_wpT + 256, 512);
    k_transpose_g<<<dim3(16, 32), tb>>>(wih0, 1024, 512, p_wih0Tg);
    k_transpose_g<<<dim3(8, 32),  tb>>>(whh0, 1024, 256, p_whh0Tg);
    k_transpose_g<<<dim3(8, 32),  tb>>>(wih1, 1024, 256, p_w1Tg);
    k_transpose_g<<<dim3(8, 32),  tb>>>(whh1, 1024, 256, p_w1Tg + 256 * 1024);
    k_transpose<<<dim3(8, 250), tb>>>(fcw,  NV, 256, p_fcT, NV);
    k_permb<<<8, 256>>>(b0, b1);
    k_gemm<<<dim3(2, 1), 256>>>(p_eo, 512, p_eo, 512, 512, 512,
                                p_wpT, 512, 512, p_pb, p_h0c0, 512, NBT);
    k_gemm<<<dim3(4, 1), 256>>>(p_h0c0, 512, p_h0c0, 512, 256, 256,
                                p_wih0Tg, 1024, 1024, p_pb0, p_gctx, 1024, NBT);
    k_xemb<<<340, 256>>>(prev, embed, stemb);
    k_gemm<<<dim3(4, 6), 256>>>(p_xemb, 256, p_xemb, 256, 256, 256,
                                p_wih0Tg + 256 * 1024, 1024, 1024, (const float*)0,
                                p_gx, 1024, NS * NBJ);
    k_init<<<1088, 256>>>();

    const int HB = NROW * NH;
    for (int s = 0; s < NS; s++) {
        float* h1r = p_h1 + (s & 1) * HB;
        float* h1w = p_h1 + ((s + 1) & 1) * HB;
        float* h2r = p_h2 + (s & 1) * HB;
        float* h2w = p_h2 + ((s + 1) & 1) * HB;
        k_lstm<<<dim3(4, 34), 256>>>(h1r, h1r, 256, p_whh0Tg,
                                     p_gctx, p_gx + (size_t)s * NBJ * 1024,
                                     p_c1, h1w);
        k_lstm<<<dim3(4, 34), 256>>>(h1w, h2r, 512, p_w1Tg,
                                     p_pb1, (const float*)0,
                                     p_c2, h2w);
        k_fc<<<dim3(32, 17), 256>>>(h2w, p_fcT, fcb, prev, s);
        k_combine<<<5, 256>>>(s);
    }
    k_dp<<<1, 128>>>(out);
}